// round 1
// baseline (speedup 1.0000x reference)
#include <cuda_runtime.h>
#include <cstdint>

#define NN 50000
#define DIM_IN 256
#define HID 64
#define JC 960          // 15*HID concat width
#define OUTC 32
#define BN_EPS 1e-5f

// Persistent scratch: J = [h(64) | c0(128) | c1(256) | c2(512)] per node row.
__device__ float d_J[(size_t)NN * JC];          // 192 MB
__device__ double d_stats[768];                  // [sum0(128), sq0(128), sum1(256), sq1(256)]
__device__ float d_scaleA[256];
__device__ float d_shiftA[256];

// ---------------- zeroing ----------------
__global__ void zero_stats_kernel() {
    int i = threadIdx.x;
    if (i < 768) d_stats[i] = 0.0;
}

__global__ void zero_J_kernel() {
    // zero columns [64, 960) of every row, as float4
    int idx = blockIdx.x * blockDim.x + threadIdx.x;
    const int per_row = (JC - HID) / 4;  // 224
    if (idx >= NN * per_row) return;
    int row = idx / per_row;
    int c4 = idx - row * per_row;
    float4* p = reinterpret_cast<float4*>(d_J + (size_t)row * JC + HID) + c4;
    *p = make_float4(0.f, 0.f, 0.f, 0.f);
}

// ---------------- embed: J[:,0:64] = relu(x @ W + b) ----------------
__global__ void embed_kernel(const float* __restrict__ x,
                             const float* __restrict__ W,
                             const float* __restrict__ b) {
    __shared__ float Ws[64][64];   // K-tile of W
    __shared__ float xs[16][64];   // 16 rows x K-tile
    const int tx = threadIdx.x;    // 0..63 (output col)
    const int ty = threadIdx.y;    // 0..3
    const int tid = ty * 64 + tx;
    const int row0 = blockIdx.x * 16;

    float acc[4] = {0.f, 0.f, 0.f, 0.f};
    for (int kt = 0; kt < 4; kt++) {
        for (int i = tid; i < 64 * 64; i += 256)
            Ws[i >> 6][i & 63] = W[(kt * 64 + (i >> 6)) * HID + (i & 63)];
        for (int i = tid; i < 16 * 64; i += 256)
            xs[i >> 6][i & 63] = x[(size_t)(row0 + (i >> 6)) * DIM_IN + kt * 64 + (i & 63)];
        __syncthreads();
#pragma unroll 16
        for (int kk = 0; kk < 64; kk++) {
            float wv = Ws[kk][tx];
#pragma unroll
            for (int r = 0; r < 4; r++) acc[r] += xs[ty * 4 + r][kk] * wv;
        }
        __syncthreads();
    }
    float bb = b[tx];
#pragma unroll
    for (int r = 0; r < 4; r++) {
        float v = acc[r] + bb;
        v = v > 0.f ? v : 0.f;
        d_J[(size_t)(row0 + ty * 4 + r) * JC + tx] = v;
    }
}

// ---------------- SpMM: out[row] += val * in[col], edge-parallel, 1 warp/edge ----------------
template <int D>
__global__ void spmm_kernel(const int* __restrict__ rows,
                            const int* __restrict__ cols,
                            const float* __restrict__ vals,
                            int nE, int in_off, int out_off) {
    int gw = (blockIdx.x * blockDim.x + threadIdx.x) >> 5;
    if (gw >= nE) return;
    int lane = threadIdx.x & 31;
    int r = __ldg(rows + gw);
    int c = __ldg(cols + gw);
    float v = __ldg(vals + gw);
    const float* src = d_J + (size_t)c * JC + in_off;
    float* dst = d_J + (size_t)r * JC + out_off;

    if constexpr (D == 64) {
        float2 xv = *reinterpret_cast<const float2*>(src + lane * 2);
        asm volatile("red.global.add.v2.f32 [%0], {%1, %2};" ::
                     "l"(dst + lane * 2), "f"(v * xv.x), "f"(v * xv.y) : "memory");
    } else {
#pragma unroll
        for (int i = 0; i < D / 128; i++) {
            float4 xv = *reinterpret_cast<const float4*>(src + i * 128 + lane * 4);
            asm volatile("red.global.add.v4.f32 [%0], {%1, %2, %3, %4};" ::
                         "l"(dst + i * 128 + lane * 4),
                         "f"(v * xv.x), "f"(v * xv.y), "f"(v * xv.z), "f"(v * xv.w) : "memory");
        }
    }
}

// ---------------- BatchNorm ----------------
__global__ void bn_stats_kernel(int off, int D, int statOff, int rowsPerBlock) {
    int f = threadIdx.x;  // blockDim.x == D
    int r0 = blockIdx.x * rowsPerBlock;
    int r1 = r0 + rowsPerBlock;
    if (r1 > NN) r1 = NN;
    float s = 0.f, q = 0.f;
    for (int r = r0; r < r1; r++) {
        float v = d_J[(size_t)r * JC + off + f];
        s += v;
        q += v * v;
    }
    atomicAdd(&d_stats[statOff + f], (double)s);
    atomicAdd(&d_stats[statOff + D + f], (double)q);
}

__global__ void bn_finalize_kernel(int D, int statOff,
                                   const float* __restrict__ gamma,
                                   const float* __restrict__ beta) {
    int f = threadIdx.x;
    if (f >= D) return;
    double m = d_stats[statOff + f] / (double)NN;
    double var = d_stats[statOff + D + f] / (double)NN - m * m;
    float sc = gamma[f] * rsqrtf((float)var + BN_EPS);
    d_scaleA[f] = sc;
    d_shiftA[f] = beta[f] - (float)m * sc;
}

__global__ void bn_apply_kernel(int off, int D) {
    int idx = blockIdx.x * blockDim.x + threadIdx.x;
    int per = D / 4;
    if (idx >= NN * per) return;
    int row = idx / per;
    int f = (idx - row * per) * 4;
    float4* p = reinterpret_cast<float4*>(d_J + (size_t)row * JC + off + f);
    float4 v = *p;
    float4 sc = *reinterpret_cast<const float4*>(d_scaleA + f);
    float4 sh = *reinterpret_cast<const float4*>(d_shiftA + f);
    v.x = v.x * sc.x + sh.x;
    v.y = v.y * sc.y + sh.y;
    v.z = v.z * sc.z + sh.z;
    v.w = v.w * sc.w + sh.w;
    *p = v;
}

// ---------------- head: out = J @ W_head + b_head ----------------
__global__ void head_kernel(const float* __restrict__ W,
                            const float* __restrict__ b,
                            float* __restrict__ out) {
    __shared__ float Ws[160][32];
    __shared__ float xs[32][160];
    const int tx = threadIdx.x;  // 0..31 (output col)
    const int ty = threadIdx.y;  // 0..7
    const int tid = ty * 32 + tx;
    const int row0 = blockIdx.x * 32;

    float acc[4] = {0.f, 0.f, 0.f, 0.f};
    for (int kt = 0; kt < 6; kt++) {
        for (int i = tid; i < 160 * 32; i += 256)
            Ws[i >> 5][i & 31] = W[(kt * 160 + (i >> 5)) * OUTC + (i & 31)];
        for (int i = tid; i < 32 * 160; i += 256) {
            int r = i / 160;
            int kk = i - r * 160;
            int row = row0 + r;
            xs[r][kk] = (row < NN) ? d_J[(size_t)row * JC + kt * 160 + kk] : 0.f;
        }
        __syncthreads();
#pragma unroll 8
        for (int kk = 0; kk < 160; kk++) {
            float wv = Ws[kk][tx];
#pragma unroll
            for (int r = 0; r < 4; r++) acc[r] += xs[ty * 4 + r][kk] * wv;
        }
        __syncthreads();
    }
    float bb = b[tx];
#pragma unroll
    for (int r = 0; r < 4; r++) {
        int row = row0 + ty * 4 + r;
        if (row < NN) out[(size_t)row * OUTC + tx] = acc[r] + bb;
    }
}

extern "C" void kernel_launch(void* const* d_in, const int* in_sizes, int n_in,
                              void* d_out, int out_size) {
    const float* x   = (const float*)d_in[0];
    const int*   e1r = (const int*)d_in[1];
    const int*   e1c = (const int*)d_in[2];
    const float* e1v = (const float*)d_in[3];
    const int*   e2r = (const int*)d_in[4];
    const int*   e2c = (const int*)d_in[5];
    const float* e2v = (const float*)d_in[6];
    const float* We  = (const float*)d_in[7];
    const float* be  = (const float*)d_in[8];
    const float* g0  = (const float*)d_in[9];
    const float* b0  = (const float*)d_in[10];
    const float* g1  = (const float*)d_in[11];
    const float* b1  = (const float*)d_in[12];
    const float* Wh  = (const float*)d_in[13];
    const float* bh  = (const float*)d_in[14];
    float* out = (float*)d_out;

    const int E1 = in_sizes[1];
    const int E2 = in_sizes[4];

    // clear accumulation regions + stats
    zero_stats_kernel<<<1, 768>>>();
    {
        int total = NN * ((JC - HID) / 4);
        zero_J_kernel<<<(total + 255) / 256, 256>>>();
    }

    // embed + relu -> J[:,0:64]
    embed_kernel<<<NN / 16, dim3(64, 4)>>>(x, We, be);

    // conv1: D=64 -> cols [64,192)
    spmm_kernel<64><<<(E1 * 32 + 255) / 256, 256>>>(e1r, e1c, e1v, E1, 0, 64);
    spmm_kernel<64><<<(E2 * 32 + 255) / 256, 256>>>(e2r, e2c, e2v, E2, 0, 128);

    // bn0 over cols [64,192), D=128
    bn_stats_kernel<<<(NN + 127) / 128, 128>>>(64, 128, 0, 128);
    bn_finalize_kernel<<<1, 128>>>(128, 0, g0, b0);
    bn_apply_kernel<<<(NN * 32 + 255) / 256, 256>>>(64, 128);

    // conv2: D=128 -> cols [192,448)
    spmm_kernel<128><<<(E1 * 32 + 255) / 256, 256>>>(e1r, e1c, e1v, E1, 64, 192);
    spmm_kernel<128><<<(E2 * 32 + 255) / 256, 256>>>(e2r, e2c, e2v, E2, 64, 320);

    // bn1 over cols [192,448), D=256
    bn_stats_kernel<<<(NN + 127) / 128, 256>>>(192, 256, 256, 128);
    bn_finalize_kernel<<<1, 256>>>(256, 256, g1, b1);
    bn_apply_kernel<<<(NN * 64 + 255) / 256, 256>>>(192, 256);

    // conv3: D=256 -> cols [448,960)
    spmm_kernel<256><<<(E1 * 32 + 255) / 256, 256>>>(e1r, e1c, e1v, E1, 192, 448);
    spmm_kernel<256><<<(E2 * 32 + 255) / 256, 256>>>(e2r, e2c, e2v, E2, 192, 704);

    // head GEMM
    head_kernel<<<(NN + 31) / 32, dim3(32, 8)>>>(Wh, bh, out);
}

// round 3
// speedup vs baseline: 1.7002x; 1.7002x over previous
#include <cuda_runtime.h>
#include <cstdint>

#define NN 50000
#define DIM_IN 256
#define HID 64
#define JC 960          // 15*HID concat width
#define OUTC 32
#define BN_EPS 1e-5f
#define E1MAX 800000
#define E2MAX 1600000

// Persistent scratch: J = [h(64) | c0(128) | c1(256) | c2(512)] per node row.
__device__ float d_J[(size_t)NN * JC];          // 192 MB
__device__ double d_stats[768];
__device__ float d_scaleA[256];
__device__ float d_shiftA[256];

// CSR-by-destination bins (built on device each launch)
__device__ int   d_deg1[NN], d_deg2[NN];
__device__ int   d_pos1[NN], d_pos2[NN];
__device__ int   d_ptr1[NN + 1], d_ptr2[NN + 1];
__device__ int   d_ecol1[E1MAX], d_ecol2[E2MAX];
__device__ float d_eval1[E1MAX], d_eval2[E2MAX];

// ---------------- zero / binning ----------------
__global__ void zero_small_kernel() {
    int i = blockIdx.x * blockDim.x + threadIdx.x;
    if (i < 768) d_stats[i] = 0.0;
    if (i < NN) { d_deg1[i] = 0; d_deg2[i] = 0; d_pos1[i] = 0; d_pos2[i] = 0; }
}

__global__ void hist_kernel(const int* __restrict__ rows, int nE, int which) {
    int i = blockIdx.x * blockDim.x + threadIdx.x;
    if (i >= nE) return;
    int r = rows[i];
    atomicAdd(which ? &d_deg2[r] : &d_deg1[r], 1);
}

// two blocks: blockIdx 0 scans graph1 deg -> ptr, blockIdx 1 graph2
__global__ void scan2_kernel() {
    const int* deg = blockIdx.x ? d_deg2 : d_deg1;
    int* ptr = blockIdx.x ? d_ptr2 : d_ptr1;
    __shared__ int sh[1024];
    __shared__ int carryS;
    int tx = threadIdx.x;
    if (tx == 0) carryS = 0;
    __syncthreads();
    for (int base = 0; base < NN; base += 1024) {
        int i = base + tx;
        int v = (i < NN) ? deg[i] : 0;
        sh[tx] = v;
        __syncthreads();
        for (int off = 1; off < 1024; off <<= 1) {
            int t = (tx >= off) ? sh[tx - off] : 0;
            __syncthreads();
            sh[tx] += t;
            __syncthreads();
        }
        int mycarry = carryS;
        if (i < NN) ptr[i] = mycarry + sh[tx] - v;
        int total = sh[1023];
        __syncthreads();
        if (tx == 0) carryS = mycarry + total;
        __syncthreads();
    }
    if (tx == 0) ptr[NN] = carryS;
}

__global__ void scatter_kernel(const int* __restrict__ rows,
                               const int* __restrict__ cols,
                               const float* __restrict__ vals,
                               int nE, int which) {
    int i = blockIdx.x * blockDim.x + threadIdx.x;
    if (i >= nE) return;
    int r = rows[i];
    if (which) {
        int p = d_ptr2[r] + atomicAdd(&d_pos2[r], 1);
        d_ecol2[p] = cols[i]; d_eval2[p] = vals[i];
    } else {
        int p = d_ptr1[r] + atomicAdd(&d_pos1[r], 1);
        d_ecol1[p] = cols[i]; d_eval1[p] = vals[i];
    }
}

// ---------------- embed: J[:,0:64] = relu(x @ W + b) ----------------
__global__ void embed_kernel(const float* __restrict__ x,
                             const float* __restrict__ W,
                             const float* __restrict__ b) {
    __shared__ float Ws[64][64];
    __shared__ float xs[16][64];
    const int tx = threadIdx.x;
    const int ty = threadIdx.y;
    const int tid = ty * 64 + tx;
    const int row0 = blockIdx.x * 16;

    float acc[4] = {0.f, 0.f, 0.f, 0.f};
    for (int kt = 0; kt < 4; kt++) {
        for (int i = tid; i < 64 * 64; i += 256)
            Ws[i >> 6][i & 63] = W[(kt * 64 + (i >> 6)) * HID + (i & 63)];
        for (int i = tid; i < 16 * 64; i += 256)
            xs[i >> 6][i & 63] = x[(size_t)(row0 + (i >> 6)) * DIM_IN + kt * 64 + (i & 63)];
        __syncthreads();
#pragma unroll 16
        for (int kk = 0; kk < 64; kk++) {
            float wv = Ws[kk][tx];
#pragma unroll
            for (int r = 0; r < 4; r++) acc[r] += xs[ty * 4 + r][kk] * wv;
        }
        __syncthreads();
    }
    float bb = b[tx];
#pragma unroll
    for (int r = 0; r < 4; r++) {
        float v = acc[r] + bb;
        v = v > 0.f ? v : 0.f;
        d_J[(size_t)(row0 + ty * 4 + r) * JC + tx] = v;
    }
}

// ---------------- SpMM gather: warp per dest row, register accumulate ----------------
template <int C>  // floats per lane; D = 32*C
__device__ __forceinline__ void accum_row(float* acc, const float* __restrict__ src,
                                          int lane, float v) {
    if constexpr (C == 2) {
        float2 x = *reinterpret_cast<const float2*>(src + lane * 2);
        acc[0] += v * x.x; acc[1] += v * x.y;
    } else if constexpr (C == 4) {
        float4 x = *reinterpret_cast<const float4*>(src + lane * 4);
        acc[0] += v * x.x; acc[1] += v * x.y; acc[2] += v * x.z; acc[3] += v * x.w;
    } else {
        float4 xa = *reinterpret_cast<const float4*>(src + lane * 4);
        float4 xb = *reinterpret_cast<const float4*>(src + 128 + lane * 4);
        acc[0] += v * xa.x; acc[1] += v * xa.y; acc[2] += v * xa.z; acc[3] += v * xa.w;
        acc[4] += v * xb.x; acc[5] += v * xb.y; acc[6] += v * xb.z; acc[7] += v * xb.w;
    }
}

template <int C, int G>  // G: which graph's CSR (selected in DEVICE code)
__global__ void spmm_gather_kernel(int in_off, int out_off) {
    const int* __restrict__ ptr   = (G == 0) ? d_ptr1  : d_ptr2;
    const int* __restrict__ ecol  = (G == 0) ? d_ecol1 : d_ecol2;
    const float* __restrict__ eval = (G == 0) ? d_eval1 : d_eval2;

    int row = (blockIdx.x * blockDim.x + threadIdx.x) >> 5;
    if (row >= NN) return;
    int lane = threadIdx.x & 31;
    int s = __ldg(ptr + row), e = __ldg(ptr + row + 1);
    float acc[C];
#pragma unroll
    for (int i = 0; i < C; i++) acc[i] = 0.f;

    for (int b = s; b < e; b += 32) {
        int n = min(32, e - b);
        int cc = 0; float vv = 0.f;
        if (lane < n) { cc = __ldg(ecol + b + lane); vv = __ldg(eval + b + lane); }
        int j = 0;
        for (; j + 4 <= n; j += 4) {
            int c0 = __shfl_sync(0xffffffffu, cc, j);
            int c1 = __shfl_sync(0xffffffffu, cc, j + 1);
            int c2 = __shfl_sync(0xffffffffu, cc, j + 2);
            int c3 = __shfl_sync(0xffffffffu, cc, j + 3);
            float v0 = __shfl_sync(0xffffffffu, vv, j);
            float v1 = __shfl_sync(0xffffffffu, vv, j + 1);
            float v2 = __shfl_sync(0xffffffffu, vv, j + 2);
            float v3 = __shfl_sync(0xffffffffu, vv, j + 3);
            accum_row<C>(acc, d_J + (size_t)c0 * JC + in_off, lane, v0);
            accum_row<C>(acc, d_J + (size_t)c1 * JC + in_off, lane, v1);
            accum_row<C>(acc, d_J + (size_t)c2 * JC + in_off, lane, v2);
            accum_row<C>(acc, d_J + (size_t)c3 * JC + in_off, lane, v3);
        }
        for (; j < n; j++) {
            int cj = __shfl_sync(0xffffffffu, cc, j);
            float vj = __shfl_sync(0xffffffffu, vv, j);
            accum_row<C>(acc, d_J + (size_t)cj * JC + in_off, lane, vj);
        }
    }

    float* dst = d_J + (size_t)row * JC + out_off;
    if constexpr (C == 2) {
        *reinterpret_cast<float2*>(dst + lane * 2) = make_float2(acc[0], acc[1]);
    } else if constexpr (C == 4) {
        *reinterpret_cast<float4*>(dst + lane * 4) = make_float4(acc[0], acc[1], acc[2], acc[3]);
    } else {
        *reinterpret_cast<float4*>(dst + lane * 4) = make_float4(acc[0], acc[1], acc[2], acc[3]);
        *reinterpret_cast<float4*>(dst + 128 + lane * 4) = make_float4(acc[4], acc[5], acc[6], acc[7]);
    }
}

// ---------------- BatchNorm ----------------
__global__ void bn_stats_kernel(int off, int D, int statOff, int rowsPerBlock) {
    int f = threadIdx.x;
    int r0 = blockIdx.x * rowsPerBlock;
    int r1 = r0 + rowsPerBlock;
    if (r1 > NN) r1 = NN;
    float s = 0.f, q = 0.f;
    for (int r = r0; r < r1; r++) {
        float v = d_J[(size_t)r * JC + off + f];
        s += v;
        q += v * v;
    }
    atomicAdd(&d_stats[statOff + f], (double)s);
    atomicAdd(&d_stats[statOff + D + f], (double)q);
}

__global__ void bn_finalize_kernel(int D, int statOff,
                                   const float* __restrict__ gamma,
                                   const float* __restrict__ beta) {
    int f = threadIdx.x;
    if (f >= D) return;
    double m = d_stats[statOff + f] / (double)NN;
    double var = d_stats[statOff + D + f] / (double)NN - m * m;
    float sc = gamma[f] * rsqrtf((float)var + BN_EPS);
    d_scaleA[f] = sc;
    d_shiftA[f] = beta[f] - (float)m * sc;
}

__global__ void bn_apply_kernel(int off, int D) {
    int idx = blockIdx.x * blockDim.x + threadIdx.x;
    int per = D / 4;
    if (idx >= NN * per) return;
    int row = idx / per;
    int f = (idx - row * per) * 4;
    float4* p = reinterpret_cast<float4*>(d_J + (size_t)row * JC + off + f);
    float4 v = *p;
    float4 sc = *reinterpret_cast<const float4*>(d_scaleA + f);
    float4 sh = *reinterpret_cast<const float4*>(d_shiftA + f);
    v.x = v.x * sc.x + sh.x;
    v.y = v.y * sc.y + sh.y;
    v.z = v.z * sc.z + sh.z;
    v.w = v.w * sc.w + sh.w;
    *p = v;
}

// ---------------- head: out = J @ W_head + b_head ----------------
__global__ void head_kernel(const float* __restrict__ W,
                            const float* __restrict__ b,
                            float* __restrict__ out) {
    __shared__ float Ws[160][32];
    __shared__ float xs[32][160];
    const int tx = threadIdx.x;
    const int ty = threadIdx.y;
    const int tid = ty * 32 + tx;
    const int row0 = blockIdx.x * 32;

    float acc[4] = {0.f, 0.f, 0.f, 0.f};
    for (int kt = 0; kt < 6; kt++) {
        for (int i = tid; i < 160 * 32; i += 256)
            Ws[i >> 5][i & 31] = W[(kt * 160 + (i >> 5)) * OUTC + (i & 31)];
        for (int i = tid; i < 32 * 160; i += 256) {
            int r = i / 160;
            int kk = i - r * 160;
            int row = row0 + r;
            xs[r][kk] = (row < NN) ? d_J[(size_t)row * JC + kt * 160 + kk] : 0.f;
        }
        __syncthreads();
#pragma unroll 8
        for (int kk = 0; kk < 160; kk++) {
            float wv = Ws[kk][tx];
#pragma unroll
            for (int r = 0; r < 4; r++) acc[r] += xs[ty * 4 + r][kk] * wv;
        }
        __syncthreads();
    }
    float bb = b[tx];
#pragma unroll
    for (int r = 0; r < 4; r++) {
        int row = row0 + ty * 4 + r;
        if (row < NN) out[(size_t)row * OUTC + tx] = acc[r] + bb;
    }
}

extern "C" void kernel_launch(void* const* d_in, const int* in_sizes, int n_in,
                              void* d_out, int out_size) {
    const float* x   = (const float*)d_in[0];
    const int*   e1r = (const int*)d_in[1];
    const int*   e1c = (const int*)d_in[2];
    const float* e1v = (const float*)d_in[3];
    const int*   e2r = (const int*)d_in[4];
    const int*   e2c = (const int*)d_in[5];
    const float* e2v = (const float*)d_in[6];
    const float* We  = (const float*)d_in[7];
    const float* be  = (const float*)d_in[8];
    const float* g0  = (const float*)d_in[9];
    const float* b0  = (const float*)d_in[10];
    const float* g1  = (const float*)d_in[11];
    const float* b1  = (const float*)d_in[12];
    const float* Wh  = (const float*)d_in[13];
    const float* bh  = (const float*)d_in[14];
    float* out = (float*)d_out;

    const int E1 = in_sizes[1];
    const int E2 = in_sizes[4];

    // ---- binning: CSR by destination row, both graphs ----
    zero_small_kernel<<<(NN + 255) / 256, 256>>>();
    hist_kernel<<<(E1 + 255) / 256, 256>>>(e1r, E1, 0);
    hist_kernel<<<(E2 + 255) / 256, 256>>>(e2r, E2, 1);
    scan2_kernel<<<2, 1024>>>();
    scatter_kernel<<<(E1 + 255) / 256, 256>>>(e1r, e1c, e1v, E1, 0);
    scatter_kernel<<<(E2 + 255) / 256, 256>>>(e2r, e2c, e2v, E2, 1);

    // ---- embed + relu -> J[:,0:64] ----
    embed_kernel<<<NN / 16, dim3(64, 4)>>>(x, We, be);

    const int gblocks = (NN + 7) / 8;  // 8 warps (rows) per 256-thread block

    // conv1: D=64 (C=2) -> cols [64,192)
    spmm_gather_kernel<2, 0><<<gblocks, 256>>>(0, 64);
    spmm_gather_kernel<2, 1><<<gblocks, 256>>>(0, 128);

    // bn0 over cols [64,192), D=128
    bn_stats_kernel<<<(NN + 127) / 128, 128>>>(64, 128, 0, 128);
    bn_finalize_kernel<<<1, 128>>>(128, 0, g0, b0);
    bn_apply_kernel<<<(NN * 32 + 255) / 256, 256>>>(64, 128);

    // conv2: D=128 (C=4) -> cols [192,448)
    spmm_gather_kernel<4, 0><<<gblocks, 256>>>(64, 192);
    spmm_gather_kernel<4, 1><<<gblocks, 256>>>(64, 320);

    // bn1 over cols [192,448), D=256
    bn_stats_kernel<<<(NN + 127) / 128, 256>>>(192, 256, 256, 128);
    bn_finalize_kernel<<<1, 256>>>(256, 256, g1, b1);
    bn_apply_kernel<<<(NN * 64 + 255) / 256, 256>>>(192, 256);

    // conv3: D=256 (C=8) -> cols [448,960)
    spmm_gather_kernel<8, 0><<<gblocks, 256>>>(192, 448);
    spmm_gather_kernel<8, 1><<<gblocks, 256>>>(192, 704);

    // head GEMM
    head_kernel<<<(NN + 31) / 32, dim3(32, 8)>>>(Wh, bh, out);
}

// round 4
// speedup vs baseline: 1.8470x; 1.0864x over previous
#include <cuda_runtime.h>
#include <cstdint>

#define NN 50000
#define DIM_IN 256
#define HID 64
#define JC 960          // 15*HID concat width
#define OUTC 32
#define BN_EPS 1e-5f
#define E1MAX 800000
#define E2MAX 1600000
#define NBLK 196        // ceil(NN/256)

// Persistent scratch: J = [h(64) | c0(128) | c1(256) | c2(512)] per node row.
__device__ float d_J[(size_t)NN * JC];          // 192 MB
__device__ double d_stats[768];
__device__ float d_scaleA[256];
__device__ float d_shiftA[256];

// CSR-by-destination bins (built on device each launch)
__device__ int   d_deg1[NN], d_deg2[NN];
__device__ int   d_pos1[NN], d_pos2[NN];
__device__ int   d_ptr1[NN + 1], d_ptr2[NN + 1];
__device__ int   d_tmp1[NN], d_tmp2[NN];        // per-block inclusive scans
__device__ int   d_bsum[2][256], d_boff[2][256];
__device__ int   d_ecol1[E1MAX], d_ecol2[E2MAX];
__device__ float d_eval1[E1MAX], d_eval2[E2MAX];

// ---------------- zero / binning ----------------
__global__ void zero_small_kernel() {
    int i = blockIdx.x * blockDim.x + threadIdx.x;
    if (i < 768) d_stats[i] = 0.0;
    if (i < NN) { d_deg1[i] = 0; d_deg2[i] = 0; d_pos1[i] = 0; d_pos2[i] = 0; }
}

__global__ void hist_kernel(const int* __restrict__ rows, int nE, int which) {
    int i = blockIdx.x * blockDim.x + threadIdx.x;
    if (i >= nE) return;
    int r = rows[i];
    atomicAdd(which ? &d_deg2[r] : &d_deg1[r], 1);
}

// Phase A: per-block inclusive scan of deg -> tmp, block totals -> d_bsum.
// grid = 2*NBLK; blockIdx.x < NBLK handles graph1.
__global__ void scan_partial_kernel() {
    int g = blockIdx.x / NBLK;
    int blk = blockIdx.x - g * NBLK;
    const int* deg = g ? d_deg2 : d_deg1;
    int* tmp = g ? d_tmp2 : d_tmp1;

    int tid = threadIdx.x;           // 0..255
    int lane = tid & 31, w = tid >> 5;
    int i = blk * 256 + tid;
    int orig = (i < NN) ? deg[i] : 0;
    int v = orig;
#pragma unroll
    for (int o = 1; o < 32; o <<= 1) {
        int t = __shfl_up_sync(0xffffffffu, v, o);
        if (lane >= o) v += t;
    }
    __shared__ int wsum[8];
    if (lane == 31) wsum[w] = v;
    __syncthreads();
    if (w == 0) {
        int s = (lane < 8) ? wsum[lane] : 0;
#pragma unroll
        for (int o = 1; o < 8; o <<= 1) {
            int t = __shfl_up_sync(0xffffffffu, s, o);
            if (lane >= o) s += t;
        }
        if (lane < 8) wsum[lane] = s;
    }
    __syncthreads();
    int incl = v + (w > 0 ? wsum[w - 1] : 0);
    if (i < NN) tmp[i] = incl;
    if (tid == 255) d_bsum[g][blk] = incl;
}

// Phase B: one block of 512 threads scans both graphs' block sums (exclusive).
__global__ void scan_tops_kernel() {
    __shared__ int sh[2][256];
    int g = threadIdx.x >> 8;
    int t = threadIdx.x & 255;
    int orig = (t < NBLK) ? d_bsum[g][t] : 0;
    sh[g][t] = orig;
    __syncthreads();
    for (int off = 1; off < 256; off <<= 1) {
        int add = (t >= off) ? sh[g][t - off] : 0;
        __syncthreads();
        sh[g][t] += add;
        __syncthreads();
    }
    d_boff[g][t] = sh[g][t] - orig;   // exclusive prefix of block sums
}

// Phase C: ptr[i] = tmp[i] - deg[i] + boff; last element writes ptr[NN].
__global__ void scan_add_kernel() {
    int g = blockIdx.x / NBLK;
    int blk = blockIdx.x - g * NBLK;
    int i = blk * 256 + threadIdx.x;
    if (i >= NN) return;
    const int* deg = g ? d_deg2 : d_deg1;
    const int* tmp = g ? d_tmp2 : d_tmp1;
    int* ptr = g ? d_ptr2 : d_ptr1;
    int off = d_boff[g][blk];
    int incl = tmp[i] + off;
    ptr[i] = incl - deg[i];
    if (i == NN - 1) ptr[NN] = incl;
}

__global__ void scatter_kernel(const int* __restrict__ rows,
                               const int* __restrict__ cols,
                               const float* __restrict__ vals,
                               int nE, int which) {
    int i = blockIdx.x * blockDim.x + threadIdx.x;
    if (i >= nE) return;
    int r = rows[i];
    if (which) {
        int p = d_ptr2[r] + atomicAdd(&d_pos2[r], 1);
        d_ecol2[p] = cols[i]; d_eval2[p] = vals[i];
    } else {
        int p = d_ptr1[r] + atomicAdd(&d_pos1[r], 1);
        d_ecol1[p] = cols[i]; d_eval1[p] = vals[i];
    }
}

// ---------------- embed: J[:,0:64] = relu(x @ W + b) ----------------
__global__ void embed_kernel(const float* __restrict__ x,
                             const float* __restrict__ W,
                             const float* __restrict__ b) {
    __shared__ float Ws[64][64];
    __shared__ float xs[16][64];
    const int tx = threadIdx.x;
    const int ty = threadIdx.y;
    const int tid = ty * 64 + tx;
    const int row0 = blockIdx.x * 16;

    float acc[4] = {0.f, 0.f, 0.f, 0.f};
    for (int kt = 0; kt < 4; kt++) {
        for (int i = tid; i < 64 * 64; i += 256)
            Ws[i >> 6][i & 63] = W[(kt * 64 + (i >> 6)) * HID + (i & 63)];
        for (int i = tid; i < 16 * 64; i += 256)
            xs[i >> 6][i & 63] = x[(size_t)(row0 + (i >> 6)) * DIM_IN + kt * 64 + (i & 63)];
        __syncthreads();
#pragma unroll 16
        for (int kk = 0; kk < 64; kk++) {
            float wv = Ws[kk][tx];
#pragma unroll
            for (int r = 0; r < 4; r++) acc[r] += xs[ty * 4 + r][kk] * wv;
        }
        __syncthreads();
    }
    float bb = b[tx];
#pragma unroll
    for (int r = 0; r < 4; r++) {
        float v = acc[r] + bb;
        v = v > 0.f ? v : 0.f;
        d_J[(size_t)(row0 + ty * 4 + r) * JC + tx] = v;
    }
}

// ---------------- SpMM gather: warp per dest row, register accumulate ----------------
template <int C>  // floats per lane; D = 32*C
__device__ __forceinline__ void accum_row(float* acc, const float* __restrict__ src,
                                          int lane, float v) {
    if constexpr (C == 2) {
        float2 x = *reinterpret_cast<const float2*>(src + lane * 2);
        acc[0] += v * x.x; acc[1] += v * x.y;
    } else if constexpr (C == 4) {
        float4 x = *reinterpret_cast<const float4*>(src + lane * 4);
        acc[0] += v * x.x; acc[1] += v * x.y; acc[2] += v * x.z; acc[3] += v * x.w;
    } else {
        float4 xa = *reinterpret_cast<const float4*>(src + lane * 4);
        float4 xb = *reinterpret_cast<const float4*>(src + 128 + lane * 4);
        acc[0] += v * xa.x; acc[1] += v * xa.y; acc[2] += v * xa.z; acc[3] += v * xa.w;
        acc[4] += v * xb.x; acc[5] += v * xb.y; acc[6] += v * xb.z; acc[7] += v * xb.w;
    }
}

template <int C, int G>  // G: which graph's CSR (selected in DEVICE code)
__global__ void spmm_gather_kernel(int in_off, int out_off) {
    const int* __restrict__ ptr   = (G == 0) ? d_ptr1  : d_ptr2;
    const int* __restrict__ ecol  = (G == 0) ? d_ecol1 : d_ecol2;
    const float* __restrict__ eval = (G == 0) ? d_eval1 : d_eval2;

    int row = (blockIdx.x * blockDim.x + threadIdx.x) >> 5;
    if (row >= NN) return;
    int lane = threadIdx.x & 31;
    int s = __ldg(ptr + row), e = __ldg(ptr + row + 1);
    float acc[C];
#pragma unroll
    for (int i = 0; i < C; i++) acc[i] = 0.f;

    for (int b = s; b < e; b += 32) {
        int n = min(32, e - b);
        int cc = 0; float vv = 0.f;
        if (lane < n) { cc = __ldg(ecol + b + lane); vv = __ldg(eval + b + lane); }
        int j = 0;
        for (; j + 8 <= n; j += 8) {
#pragma unroll
            for (int u = 0; u < 8; u++) {
                int cj = __shfl_sync(0xffffffffu, cc, j + u);
                float vj = __shfl_sync(0xffffffffu, vv, j + u);
                accum_row<C>(acc, d_J + (size_t)cj * JC + in_off, lane, vj);
            }
        }
        for (; j < n; j++) {
            int cj = __shfl_sync(0xffffffffu, cc, j);
            float vj = __shfl_sync(0xffffffffu, vv, j);
            accum_row<C>(acc, d_J + (size_t)cj * JC + in_off, lane, vj);
        }
    }

    float* dst = d_J + (size_t)row * JC + out_off;
    if constexpr (C == 2) {
        *reinterpret_cast<float2*>(dst + lane * 2) = make_float2(acc[0], acc[1]);
    } else if constexpr (C == 4) {
        *reinterpret_cast<float4*>(dst + lane * 4) = make_float4(acc[0], acc[1], acc[2], acc[3]);
    } else {
        *reinterpret_cast<float4*>(dst + lane * 4) = make_float4(acc[0], acc[1], acc[2], acc[3]);
        *reinterpret_cast<float4*>(dst + 128 + lane * 4) = make_float4(acc[4], acc[5], acc[6], acc[7]);
    }
}

// ---------------- BatchNorm ----------------
__global__ void bn_stats_kernel(int off, int D, int statOff, int rowsPerBlock) {
    int f = threadIdx.x;
    int r0 = blockIdx.x * rowsPerBlock;
    int r1 = r0 + rowsPerBlock;
    if (r1 > NN) r1 = NN;
    float s = 0.f, q = 0.f;
    for (int r = r0; r < r1; r++) {
        float v = d_J[(size_t)r * JC + off + f];
        s += v;
        q += v * v;
    }
    atomicAdd(&d_stats[statOff + f], (double)s);
    atomicAdd(&d_stats[statOff + D + f], (double)q);
}

__global__ void bn_finalize_kernel(int D, int statOff,
                                   const float* __restrict__ gamma,
                                   const float* __restrict__ beta) {
    int f = threadIdx.x;
    if (f >= D) return;
    double m = d_stats[statOff + f] / (double)NN;
    double var = d_stats[statOff + D + f] / (double)NN - m * m;
    float sc = gamma[f] * rsqrtf((float)var + BN_EPS);
    d_scaleA[f] = sc;
    d_shiftA[f] = beta[f] - (float)m * sc;
}

__global__ void bn_apply_kernel(int off, int D) {
    int idx = blockIdx.x * blockDim.x + threadIdx.x;
    int per = D / 4;
    if (idx >= NN * per) return;
    int row = idx / per;
    int f = (idx - row * per) * 4;
    float4* p = reinterpret_cast<float4*>(d_J + (size_t)row * JC + off + f);
    float4 v = *p;
    float4 sc = *reinterpret_cast<const float4*>(d_scaleA + f);
    float4 sh = *reinterpret_cast<const float4*>(d_shiftA + f);
    v.x = v.x * sc.x + sh.x;
    v.y = v.y * sc.y + sh.y;
    v.z = v.z * sc.z + sh.z;
    v.w = v.w * sc.w + sh.w;
    *p = v;
}

// ---------------- head: out = J @ W_head + b_head ----------------
__global__ void head_kernel(const float* __restrict__ W,
                            const float* __restrict__ b,
                            float* __restrict__ out) {
    __shared__ float Ws[160][32];
    __shared__ float xs[32][160];
    const int tx = threadIdx.x;
    const int ty = threadIdx.y;
    const int tid = ty * 32 + tx;
    const int row0 = blockIdx.x * 32;

    float acc[4] = {0.f, 0.f, 0.f, 0.f};
    for (int kt = 0; kt < 6; kt++) {
        for (int i = tid; i < 160 * 32; i += 256)
            Ws[i >> 5][i & 31] = W[(kt * 160 + (i >> 5)) * OUTC + (i & 31)];
        for (int i = tid; i < 32 * 160; i += 256) {
            int r = i / 160;
            int kk = i - r * 160;
            int row = row0 + r;
            xs[r][kk] = (row < NN) ? d_J[(size_t)row * JC + kt * 160 + kk] : 0.f;
        }
        __syncthreads();
#pragma unroll 8
        for (int kk = 0; kk < 160; kk++) {
            float wv = Ws[kk][tx];
#pragma unroll
            for (int r = 0; r < 4; r++) acc[r] += xs[ty * 4 + r][kk] * wv;
        }
        __syncthreads();
    }
    float bb = b[tx];
#pragma unroll
    for (int r = 0; r < 4; r++) {
        int row = row0 + ty * 4 + r;
        if (row < NN) out[(size_t)row * OUTC + tx] = acc[r] + bb;
    }
}

extern "C" void kernel_launch(void* const* d_in, const int* in_sizes, int n_in,
                              void* d_out, int out_size) {
    const float* x   = (const float*)d_in[0];
    const int*   e1r = (const int*)d_in[1];
    const int*   e1c = (const int*)d_in[2];
    const float* e1v = (const float*)d_in[3];
    const int*   e2r = (const int*)d_in[4];
    const int*   e2c = (const int*)d_in[5];
    const float* e2v = (const float*)d_in[6];
    const float* We  = (const float*)d_in[7];
    const float* be  = (const float*)d_in[8];
    const float* g0  = (const float*)d_in[9];
    const float* b0  = (const float*)d_in[10];
    const float* g1  = (const float*)d_in[11];
    const float* b1  = (const float*)d_in[12];
    const float* Wh  = (const float*)d_in[13];
    const float* bh  = (const float*)d_in[14];
    float* out = (float*)d_out;

    const int E1 = in_sizes[1];
    const int E2 = in_sizes[4];

    // ---- binning: CSR by destination row, both graphs ----
    zero_small_kernel<<<(NN + 255) / 256, 256>>>();
    hist_kernel<<<(E1 + 255) / 256, 256>>>(e1r, E1, 0);
    hist_kernel<<<(E2 + 255) / 256, 256>>>(e2r, E2, 1);
    scan_partial_kernel<<<2 * NBLK, 256>>>();
    scan_tops_kernel<<<1, 512>>>();
    scan_add_kernel<<<2 * NBLK, 256>>>();
    scatter_kernel<<<(E1 + 255) / 256, 256>>>(e1r, e1c, e1v, E1, 0);
    scatter_kernel<<<(E2 + 255) / 256, 256>>>(e2r, e2c, e2v, E2, 1);

    // ---- embed + relu -> J[:,0:64] ----
    embed_kernel<<<NN / 16, dim3(64, 4)>>>(x, We, be);

    const int gblocks = (NN + 7) / 8;  // 8 warps (rows) per 256-thread block

    // conv1: D=64 (C=2) -> cols [64,192)
    spmm_gather_kernel<2, 0><<<gblocks, 256>>>(0, 64);
    spmm_gather_kernel<2, 1><<<gblocks, 256>>>(0, 128);

    // bn0 over cols [64,192), D=128
    bn_stats_kernel<<<(NN + 127) / 128, 128>>>(64, 128, 0, 128);
    bn_finalize_kernel<<<1, 128>>>(128, 0, g0, b0);
    bn_apply_kernel<<<(NN * 32 + 255) / 256, 256>>>(64, 128);

    // conv2: D=128 (C=4) -> cols [192,448)
    spmm_gather_kernel<4, 0><<<gblocks, 256>>>(64, 192);
    spmm_gather_kernel<4, 1><<<gblocks, 256>>>(64, 320);

    // bn1 over cols [192,448), D=256
    bn_stats_kernel<<<(NN + 127) / 128, 256>>>(192, 256, 256, 128);
    bn_finalize_kernel<<<1, 256>>>(256, 256, g1, b1);
    bn_apply_kernel<<<(NN * 64 + 255) / 256, 256>>>(192, 256);

    // conv3: D=256 (C=8) -> cols [448,960)
    spmm_gather_kernel<8, 0><<<gblocks, 256>>>(192, 448);
    spmm_gather_kernel<8, 1><<<gblocks, 256>>>(192, 704);

    // head GEMM
    head_kernel<<<(NN + 31) / 32, dim3(32, 8)>>>(Wh, bh, out);
}

// round 5
// speedup vs baseline: 1.9975x; 1.0815x over previous
#include <cuda_runtime.h>
#include <cstdint>

#define NN 50000
#define DIM_IN 256
#define HID 64
#define JC 960          // 15*HID concat width
#define OUTC 32
#define BN_EPS 1e-5f
#define E1MAX 800000
#define E2MAX 1600000
#define NBLK 196        // ceil(NN/256)

// Persistent scratch: J = [h(64) | c0(128) | c1(256) | c2(512)] per node row.
__device__ float d_J[(size_t)NN * JC];          // 192 MB
__device__ double d_stats[768];
__device__ float d_scaleA[256];
__device__ float d_shiftA[256];

// CSR-by-destination bins (built on device each launch)
__device__ int   d_deg1[NN], d_deg2[NN];
__device__ int   d_pos1[NN], d_pos2[NN];
__device__ int   d_ptr1[NN + 1], d_ptr2[NN + 1];
__device__ int   d_tmp1[NN], d_tmp2[NN];
__device__ int   d_bsum[2][256], d_boff[2][256];
__device__ int2  d_e1[E1MAX], d_e2[E2MAX];      // packed (col, val_bits)

// ---------------- zero / binning ----------------
__global__ void zero_small_kernel() {
    int i = blockIdx.x * blockDim.x + threadIdx.x;
    if (i < 768) d_stats[i] = 0.0;
    if (i < NN) { d_deg1[i] = 0; d_deg2[i] = 0; d_pos1[i] = 0; d_pos2[i] = 0; }
}

__global__ void hist_kernel(const int* __restrict__ rows, int nE, int which) {
    int i = blockIdx.x * blockDim.x + threadIdx.x;
    if (i >= nE) return;
    int r = rows[i];
    atomicAdd(which ? &d_deg2[r] : &d_deg1[r], 1);
}

// Phase A: per-block inclusive scan of deg -> tmp, block totals -> d_bsum.
__global__ void scan_partial_kernel() {
    int g = blockIdx.x / NBLK;
    int blk = blockIdx.x - g * NBLK;
    const int* deg = g ? d_deg2 : d_deg1;
    int* tmp = g ? d_tmp2 : d_tmp1;

    int tid = threadIdx.x;
    int lane = tid & 31, w = tid >> 5;
    int i = blk * 256 + tid;
    int orig = (i < NN) ? deg[i] : 0;
    int v = orig;
#pragma unroll
    for (int o = 1; o < 32; o <<= 1) {
        int t = __shfl_up_sync(0xffffffffu, v, o);
        if (lane >= o) v += t;
    }
    __shared__ int wsum[8];
    if (lane == 31) wsum[w] = v;
    __syncthreads();
    if (w == 0) {
        int s = (lane < 8) ? wsum[lane] : 0;
#pragma unroll
        for (int o = 1; o < 8; o <<= 1) {
            int t = __shfl_up_sync(0xffffffffu, s, o);
            if (lane >= o) s += t;
        }
        if (lane < 8) wsum[lane] = s;
    }
    __syncthreads();
    int incl = v + (w > 0 ? wsum[w - 1] : 0);
    if (i < NN) tmp[i] = incl;
    if (tid == 255) d_bsum[g][blk] = incl;
}

// Phase B: one block scans both graphs' block sums (exclusive).
__global__ void scan_tops_kernel() {
    __shared__ int sh[2][256];
    int g = threadIdx.x >> 8;
    int t = threadIdx.x & 255;
    int orig = (t < NBLK) ? d_bsum[g][t] : 0;
    sh[g][t] = orig;
    __syncthreads();
    for (int off = 1; off < 256; off <<= 1) {
        int add = (t >= off) ? sh[g][t - off] : 0;
        __syncthreads();
        sh[g][t] += add;
        __syncthreads();
    }
    d_boff[g][t] = sh[g][t] - orig;
}

// Phase C: ptr[i] = tmp[i] - deg[i] + boff; last element writes ptr[NN].
__global__ void scan_add_kernel() {
    int g = blockIdx.x / NBLK;
    int blk = blockIdx.x - g * NBLK;
    int i = blk * 256 + threadIdx.x;
    if (i >= NN) return;
    const int* deg = g ? d_deg2 : d_deg1;
    const int* tmp = g ? d_tmp2 : d_tmp1;
    int* ptr = g ? d_ptr2 : d_ptr1;
    int off = d_boff[g][blk];
    int incl = tmp[i] + off;
    ptr[i] = incl - deg[i];
    if (i == NN - 1) ptr[NN] = incl;
}

__global__ void scatter_kernel(const int* __restrict__ rows,
                               const int* __restrict__ cols,
                               const float* __restrict__ vals,
                               int nE, int which) {
    int i = blockIdx.x * blockDim.x + threadIdx.x;
    if (i >= nE) return;
    int r = rows[i];
    int2 e = make_int2(cols[i], __float_as_int(vals[i]));
    if (which) {
        int p = d_ptr2[r] + atomicAdd(&d_pos2[r], 1);
        d_e2[p] = e;
    } else {
        int p = d_ptr1[r] + atomicAdd(&d_pos1[r], 1);
        d_e1[p] = e;
    }
}

// ---------------- embed: J[:,0:64] = relu(x @ W + b) ----------------
__global__ void embed_kernel(const float* __restrict__ x,
                             const float* __restrict__ W,
                             const float* __restrict__ b) {
    __shared__ float Ws[64][64];
    __shared__ float xs[16][64];
    const int tx = threadIdx.x;
    const int ty = threadIdx.y;
    const int tid = ty * 64 + tx;
    const int row0 = blockIdx.x * 16;

    float acc[4] = {0.f, 0.f, 0.f, 0.f};
    for (int kt = 0; kt < 4; kt++) {
        for (int i = tid; i < 64 * 64; i += 256)
            Ws[i >> 6][i & 63] = W[(kt * 64 + (i >> 6)) * HID + (i & 63)];
        for (int i = tid; i < 16 * 64; i += 256)
            xs[i >> 6][i & 63] = x[(size_t)(row0 + (i >> 6)) * DIM_IN + kt * 64 + (i & 63)];
        __syncthreads();
#pragma unroll 16
        for (int kk = 0; kk < 64; kk++) {
            float wv = Ws[kk][tx];
#pragma unroll
            for (int r = 0; r < 4; r++) acc[r] += xs[ty * 4 + r][kk] * wv;
        }
        __syncthreads();
    }
    float bb = b[tx];
#pragma unroll
    for (int r = 0; r < 4; r++) {
        float v = acc[r] + bb;
        v = v > 0.f ? v : 0.f;
        d_J[(size_t)(row0 + ty * 4 + r) * JC + tx] = v;
    }
}

// ---------------- fused SpMM gather: warp per dest row, both graphs ----------------
template <int C>
__device__ __forceinline__ void accum_row(float* acc, const float* __restrict__ src,
                                          int lane, float v) {
    if constexpr (C == 2) {
        float2 x = *reinterpret_cast<const float2*>(src + lane * 2);
        acc[0] += v * x.x; acc[1] += v * x.y;
    } else if constexpr (C == 4) {
        float4 x = *reinterpret_cast<const float4*>(src + lane * 4);
        acc[0] += v * x.x; acc[1] += v * x.y; acc[2] += v * x.z; acc[3] += v * x.w;
    } else {
        float4 xa = *reinterpret_cast<const float4*>(src + lane * 4);
        float4 xb = *reinterpret_cast<const float4*>(src + 128 + lane * 4);
        acc[0] += v * xa.x; acc[1] += v * xa.y; acc[2] += v * xa.z; acc[3] += v * xa.w;
        acc[4] += v * xb.x; acc[5] += v * xb.y; acc[6] += v * xb.z; acc[7] += v * xb.w;
    }
}

template <int C>
__device__ __forceinline__ void gather_one(const int2* __restrict__ edges,
                                           int s, int e, const float* __restrict__ base,
                                           int lane, float* acc) {
#pragma unroll
    for (int i = 0; i < C; i++) acc[i] = 0.f;
    int j = s;
    for (; j + 8 <= e; j += 8) {
        int2 cv[8];
#pragma unroll
        for (int u = 0; u < 8; u++) cv[u] = __ldg(edges + j + u);
#pragma unroll
        for (int u = 0; u < 8; u++)
            accum_row<C>(acc, base + (size_t)cv[u].x * JC, lane, __int_as_float(cv[u].y));
    }
    for (; j < e; j++) {
        int2 cv = __ldg(edges + j);
        accum_row<C>(acc, base + (size_t)cv.x * JC, lane, __int_as_float(cv.y));
    }
}

template <int C>
__device__ __forceinline__ void store_acc(float* dst, int lane, const float* acc) {
    if constexpr (C == 2) {
        *reinterpret_cast<float2*>(dst + lane * 2) = make_float2(acc[0], acc[1]);
    } else if constexpr (C == 4) {
        *reinterpret_cast<float4*>(dst + lane * 4) = make_float4(acc[0], acc[1], acc[2], acc[3]);
    } else {
        *reinterpret_cast<float4*>(dst + lane * 4) = make_float4(acc[0], acc[1], acc[2], acc[3]);
        *reinterpret_cast<float4*>(dst + 128 + lane * 4) = make_float4(acc[4], acc[5], acc[6], acc[7]);
    }
}

template <int C>  // conv layer: both graphs, D = 32*C per graph
__global__ void conv_kernel(int in_off, int out_off) {
    int row = (blockIdx.x * blockDim.x + threadIdx.x) >> 5;
    if (row >= NN) return;
    int lane = threadIdx.x & 31;
    const float* base = d_J + in_off;
    float* dst = d_J + (size_t)row * JC + out_off;
    float acc[C];

    gather_one<C>(d_e1, __ldg(d_ptr1 + row), __ldg(d_ptr1 + row + 1), base, lane, acc);
    store_acc<C>(dst, lane, acc);

    gather_one<C>(d_e2, __ldg(d_ptr2 + row), __ldg(d_ptr2 + row + 1), base, lane, acc);
    store_acc<C>(dst + 32 * C, lane, acc);
}

// ---------------- BatchNorm ----------------
__global__ void bn_stats_kernel(int off, int D, int statOff, int rowsPerBlock) {
    int f = threadIdx.x;
    int r0 = blockIdx.x * rowsPerBlock;
    int r1 = r0 + rowsPerBlock;
    if (r1 > NN) r1 = NN;
    float s = 0.f, q = 0.f;
    for (int r = r0; r < r1; r++) {
        float v = d_J[(size_t)r * JC + off + f];
        s += v;
        q += v * v;
    }
    atomicAdd(&d_stats[statOff + f], (double)s);
    atomicAdd(&d_stats[statOff + D + f], (double)q);
}

__global__ void bn_finalize_kernel(int D, int statOff,
                                   const float* __restrict__ gamma,
                                   const float* __restrict__ beta) {
    int f = threadIdx.x;
    if (f >= D) return;
    double m = d_stats[statOff + f] / (double)NN;
    double var = d_stats[statOff + D + f] / (double)NN - m * m;
    float sc = gamma[f] * rsqrtf((float)var + BN_EPS);
    d_scaleA[f] = sc;
    d_shiftA[f] = beta[f] - (float)m * sc;
}

__global__ void bn_apply_kernel(int off, int D) {
    int idx = blockIdx.x * blockDim.x + threadIdx.x;
    int per = D / 4;
    if (idx >= NN * per) return;
    int row = idx / per;
    int f = (idx - row * per) * 4;
    float4* p = reinterpret_cast<float4*>(d_J + (size_t)row * JC + off + f);
    float4 v = *p;
    float4 sc = *reinterpret_cast<const float4*>(d_scaleA + f);
    float4 sh = *reinterpret_cast<const float4*>(d_shiftA + f);
    v.x = v.x * sc.x + sh.x;
    v.y = v.y * sc.y + sh.y;
    v.z = v.z * sc.z + sh.z;
    v.w = v.w * sc.w + sh.w;
    *p = v;
}

// ---------------- head: out = J @ W_head + b_head ----------------
__global__ void head_kernel(const float* __restrict__ W,
                            const float* __restrict__ b,
                            float* __restrict__ out) {
    __shared__ float Ws[160][32];
    __shared__ float xs[32][160];
    const int tx = threadIdx.x;
    const int ty = threadIdx.y;
    const int tid = ty * 32 + tx;
    const int row0 = blockIdx.x * 32;

    float acc[4] = {0.f, 0.f, 0.f, 0.f};
    for (int kt = 0; kt < 6; kt++) {
        for (int i = tid; i < 160 * 32; i += 256)
            Ws[i >> 5][i & 31] = W[(kt * 160 + (i >> 5)) * OUTC + (i & 31)];
        for (int i = tid; i < 32 * 160; i += 256) {
            int r = i / 160;
            int kk = i - r * 160;
            int row = row0 + r;
            xs[r][kk] = (row < NN) ? d_J[(size_t)row * JC + kt * 160 + kk] : 0.f;
        }
        __syncthreads();
#pragma unroll 8
        for (int kk = 0; kk < 160; kk++) {
            float wv = Ws[kk][tx];
#pragma unroll
            for (int r = 0; r < 4; r++) acc[r] += xs[ty * 4 + r][kk] * wv;
        }
        __syncthreads();
    }
    float bb = b[tx];
#pragma unroll
    for (int r = 0; r < 4; r++) {
        int row = row0 + ty * 4 + r;
        if (row < NN) out[(size_t)row * OUTC + tx] = acc[r] + bb;
    }
}

extern "C" void kernel_launch(void* const* d_in, const int* in_sizes, int n_in,
                              void* d_out, int out_size) {
    const float* x   = (const float*)d_in[0];
    const int*   e1r = (const int*)d_in[1];
    const int*   e1c = (const int*)d_in[2];
    const float* e1v = (const float*)d_in[3];
    const int*   e2r = (const int*)d_in[4];
    const int*   e2c = (const int*)d_in[5];
    const float* e2v = (const float*)d_in[6];
    const float* We  = (const float*)d_in[7];
    const float* be  = (const float*)d_in[8];
    const float* g0  = (const float*)d_in[9];
    const float* b0  = (const float*)d_in[10];
    const float* g1  = (const float*)d_in[11];
    const float* b1  = (const float*)d_in[12];
    const float* Wh  = (const float*)d_in[13];
    const float* bh  = (const float*)d_in[14];
    float* out = (float*)d_out;

    const int E1 = in_sizes[1];
    const int E2 = in_sizes[4];

    // ---- binning: CSR by destination row, both graphs ----
    zero_small_kernel<<<(NN + 255) / 256, 256>>>();
    hist_kernel<<<(E1 + 255) / 256, 256>>>(e1r, E1, 0);
    hist_kernel<<<(E2 + 255) / 256, 256>>>(e2r, E2, 1);
    scan_partial_kernel<<<2 * NBLK, 256>>>();
    scan_tops_kernel<<<1, 512>>>();
    scan_add_kernel<<<2 * NBLK, 256>>>();
    scatter_kernel<<<(E1 + 255) / 256, 256>>>(e1r, e1c, e1v, E1, 0);
    scatter_kernel<<<(E2 + 255) / 256, 256>>>(e2r, e2c, e2v, E2, 1);

    // ---- embed + relu -> J[:,0:64] ----
    embed_kernel<<<NN / 16, dim3(64, 4)>>>(x, We, be);

    const int gblocks = (NN + 7) / 8;  // 8 warps (rows) per 256-thread block

    // conv1: D=64 per graph -> cols [64,192)
    conv_kernel<2><<<gblocks, 256>>>(0, 64);

    // bn0 over cols [64,192), D=128
    bn_stats_kernel<<<(NN + 127) / 128, 128>>>(64, 128, 0, 128);
    bn_finalize_kernel<<<1, 128>>>(128, 0, g0, b0);
    bn_apply_kernel<<<(NN * 32 + 255) / 256, 256>>>(64, 128);

    // conv2: D=128 per graph -> cols [192,448)
    conv_kernel<4><<<gblocks, 256>>>(64, 192);

    // bn1 over cols [192,448), D=256
    bn_stats_kernel<<<(NN + 127) / 128, 256>>>(192, 256, 256, 128);
    bn_finalize_kernel<<<1, 256>>>(256, 256, g1, b1);
    bn_apply_kernel<<<(NN * 64 + 255) / 256, 256>>>(192, 256);

    // conv3: D=256 per graph -> cols [448,960)
    conv_kernel<8><<<gblocks, 256>>>(192, 448);

    // head GEMM
    head_kernel<<<(NN + 31) / 32, dim3(32, 8)>>>(Wh, bh, out);
}

// round 6
// speedup vs baseline: 2.2517x; 1.1273x over previous
#include <cuda_runtime.h>
#include <cstdint>

#define NN 50000
#define DIM_IN 256
#define HID 64
#define JC 960          // 15*HID concat width
#define OUTC 32
#define BN_EPS 1e-5f
#define E1MAX 800000
#define E2MAX 1600000
#define NBLK 196        // ceil(NN/256)

// Persistent scratch: J = [h(64) | c0raw(128) | c1raw(256) | c2(512)] per row.
__device__ float d_J[(size_t)NN * JC];          // 192 MB
__device__ double d_stats[768];
__device__ float d_scale0[128], d_shift0[128];
__device__ float d_scale1[256], d_shift1[256];
__device__ float d_Wh2[JC * OUTC];
__device__ float d_bh2[OUTC];

// CSR-by-destination bins
__device__ int   d_deg1[NN], d_deg2[NN];
__device__ int   d_pos1[NN], d_pos2[NN];
__device__ int   d_ptr1[NN + 1], d_ptr2[NN + 1];
__device__ int   d_tmp1[NN], d_tmp2[NN];
__device__ int   d_bsum[2][256], d_boff[2][256];
__device__ int2  d_e1[E1MAX], d_e2[E2MAX];      // packed (col, val_bits)

// ---------------- zero / binning ----------------
__global__ void zero_small_kernel() {
    int i = blockIdx.x * blockDim.x + threadIdx.x;
    if (i < 768) d_stats[i] = 0.0;
    if (i < NN) { d_deg1[i] = 0; d_deg2[i] = 0; d_pos1[i] = 0; d_pos2[i] = 0; }
}

__global__ void hist_kernel(const int* __restrict__ rows, int nE, int which) {
    int i = blockIdx.x * blockDim.x + threadIdx.x;
    if (i >= nE) return;
    int r = rows[i];
    atomicAdd(which ? &d_deg2[r] : &d_deg1[r], 1);
}

__global__ void scan_partial_kernel() {
    int g = blockIdx.x / NBLK;
    int blk = blockIdx.x - g * NBLK;
    const int* deg = g ? d_deg2 : d_deg1;
    int* tmp = g ? d_tmp2 : d_tmp1;

    int tid = threadIdx.x;
    int lane = tid & 31, w = tid >> 5;
    int i = blk * 256 + tid;
    int orig = (i < NN) ? deg[i] : 0;
    int v = orig;
#pragma unroll
    for (int o = 1; o < 32; o <<= 1) {
        int t = __shfl_up_sync(0xffffffffu, v, o);
        if (lane >= o) v += t;
    }
    __shared__ int wsum[8];
    if (lane == 31) wsum[w] = v;
    __syncthreads();
    if (w == 0) {
        int s = (lane < 8) ? wsum[lane] : 0;
#pragma unroll
        for (int o = 1; o < 8; o <<= 1) {
            int t = __shfl_up_sync(0xffffffffu, s, o);
            if (lane >= o) s += t;
        }
        if (lane < 8) wsum[lane] = s;
    }
    __syncthreads();
    int incl = v + (w > 0 ? wsum[w - 1] : 0);
    if (i < NN) tmp[i] = incl;
    if (tid == 255) d_bsum[g][blk] = incl;
}

__global__ void scan_tops_kernel() {
    __shared__ int sh[2][256];
    int g = threadIdx.x >> 8;
    int t = threadIdx.x & 255;
    int orig = (t < NBLK) ? d_bsum[g][t] : 0;
    sh[g][t] = orig;
    __syncthreads();
    for (int off = 1; off < 256; off <<= 1) {
        int add = (t >= off) ? sh[g][t - off] : 0;
        __syncthreads();
        sh[g][t] += add;
        __syncthreads();
    }
    d_boff[g][t] = sh[g][t] - orig;
}

__global__ void scan_add_kernel() {
    int g = blockIdx.x / NBLK;
    int blk = blockIdx.x - g * NBLK;
    int i = blk * 256 + threadIdx.x;
    if (i >= NN) return;
    const int* deg = g ? d_deg2 : d_deg1;
    const int* tmp = g ? d_tmp2 : d_tmp1;
    int* ptr = g ? d_ptr2 : d_ptr1;
    int off = d_boff[g][blk];
    int incl = tmp[i] + off;
    ptr[i] = incl - deg[i];
    if (i == NN - 1) ptr[NN] = incl;
}

__global__ void scatter_kernel(const int* __restrict__ rows,
                               const int* __restrict__ cols,
                               const float* __restrict__ vals,
                               int nE, int which) {
    int i = blockIdx.x * blockDim.x + threadIdx.x;
    if (i >= nE) return;
    int r = rows[i];
    int2 e = make_int2(cols[i], __float_as_int(vals[i]));
    if (which) {
        int p = d_ptr2[r] + atomicAdd(&d_pos2[r], 1);
        d_e2[p] = e;
    } else {
        int p = d_ptr1[r] + atomicAdd(&d_pos1[r], 1);
        d_e1[p] = e;
    }
}

// ---------------- embed: J[:,0:64] = relu(x @ W + b) ----------------
__global__ void embed_kernel(const float* __restrict__ x,
                             const float* __restrict__ W,
                             const float* __restrict__ b) {
    __shared__ float Ws[64][64];
    __shared__ float xs[16][64];
    const int tx = threadIdx.x;
    const int ty = threadIdx.y;
    const int tid = ty * 64 + tx;
    const int row0 = blockIdx.x * 16;

    float acc[4] = {0.f, 0.f, 0.f, 0.f};
    for (int kt = 0; kt < 4; kt++) {
        for (int i = tid; i < 64 * 64; i += 256)
            Ws[i >> 6][i & 63] = W[(kt * 64 + (i >> 6)) * HID + (i & 63)];
        for (int i = tid; i < 16 * 64; i += 256)
            xs[i >> 6][i & 63] = x[(size_t)(row0 + (i >> 6)) * DIM_IN + kt * 64 + (i & 63)];
        __syncthreads();
#pragma unroll 16
        for (int kk = 0; kk < 64; kk++) {
            float wv = Ws[kk][tx];
#pragma unroll
            for (int r = 0; r < 4; r++) acc[r] += xs[ty * 4 + r][kk] * wv;
        }
        __syncthreads();
    }
    float bb = b[tx];
#pragma unroll
    for (int r = 0; r < 4; r++) {
        float v = acc[r] + bb;
        v = v > 0.f ? v : 0.f;
        d_J[(size_t)(row0 + ty * 4 + r) * JC + tx] = v;
    }
}

// ---------------- fused SpMM gather (+ BN fold on input) ----------------
template <int C>
__device__ __forceinline__ void accum_row(float* acc, const float* __restrict__ src,
                                          int lane, float v) {
    if constexpr (C == 2) {
        float2 x = *reinterpret_cast<const float2*>(src + lane * 2);
        acc[0] += v * x.x; acc[1] += v * x.y;
    } else if constexpr (C == 4) {
        float4 x = *reinterpret_cast<const float4*>(src + lane * 4);
        acc[0] += v * x.x; acc[1] += v * x.y; acc[2] += v * x.z; acc[3] += v * x.w;
    } else {
        float4 xa = *reinterpret_cast<const float4*>(src + lane * 4);
        float4 xb = *reinterpret_cast<const float4*>(src + 128 + lane * 4);
        acc[0] += v * xa.x; acc[1] += v * xa.y; acc[2] += v * xa.z; acc[3] += v * xa.w;
        acc[4] += v * xb.x; acc[5] += v * xb.y; acc[6] += v * xb.z; acc[7] += v * xb.w;
    }
}

template <int C>
__device__ __forceinline__ float gather_one(const int2* __restrict__ edges,
                                            int s, int e, const float* __restrict__ base,
                                            int lane, float* acc) {
#pragma unroll
    for (int i = 0; i < C; i++) acc[i] = 0.f;
    float sumv = 0.f;
    int j = s;
    for (; j + 8 <= e; j += 8) {
        int2 cv[8];
#pragma unroll
        for (int u = 0; u < 8; u++) cv[u] = __ldg(edges + j + u);
#pragma unroll
        for (int u = 0; u < 8; u++) {
            float v = __int_as_float(cv[u].y);
            sumv += v;
            accum_row<C>(acc, base + (size_t)cv[u].x * JC, lane, v);
        }
    }
    for (; j < e; j++) {
        int2 cv = __ldg(edges + j);
        float v = __int_as_float(cv.y);
        sumv += v;
        accum_row<C>(acc, base + (size_t)cv.x * JC, lane, v);
    }
    return sumv;
}

// FOLD: 0 none, 1 bn0 params, 2 bn1 params (applied to gathered input)
template <int C, int FOLD>
__device__ __forceinline__ void store_acc(float* dst, int lane, const float* acc, float sumv) {
    const float* sc = (FOLD == 1) ? d_scale0 : d_scale1;
    const float* sh = (FOLD == 1) ? d_shift0 : d_shift1;
    if constexpr (C == 2) {
        float2 o;
        if constexpr (FOLD) {
            o.x = acc[0] * sc[lane * 2] + sumv * sh[lane * 2];
            o.y = acc[1] * sc[lane * 2 + 1] + sumv * sh[lane * 2 + 1];
        } else { o.x = acc[0]; o.y = acc[1]; }
        *reinterpret_cast<float2*>(dst + lane * 2) = o;
    } else if constexpr (C == 4) {
        float4 o;
        if constexpr (FOLD) {
            o.x = acc[0] * sc[lane * 4] + sumv * sh[lane * 4];
            o.y = acc[1] * sc[lane * 4 + 1] + sumv * sh[lane * 4 + 1];
            o.z = acc[2] * sc[lane * 4 + 2] + sumv * sh[lane * 4 + 2];
            o.w = acc[3] * sc[lane * 4 + 3] + sumv * sh[lane * 4 + 3];
        } else { o.x = acc[0]; o.y = acc[1]; o.z = acc[2]; o.w = acc[3]; }
        *reinterpret_cast<float4*>(dst + lane * 4) = o;
    } else {
        float4 oa, ob;
        if constexpr (FOLD) {
            oa.x = acc[0] * sc[lane * 4] + sumv * sh[lane * 4];
            oa.y = acc[1] * sc[lane * 4 + 1] + sumv * sh[lane * 4 + 1];
            oa.z = acc[2] * sc[lane * 4 + 2] + sumv * sh[lane * 4 + 2];
            oa.w = acc[3] * sc[lane * 4 + 3] + sumv * sh[lane * 4 + 3];
            ob.x = acc[4] * sc[128 + lane * 4] + sumv * sh[128 + lane * 4];
            ob.y = acc[5] * sc[128 + lane * 4 + 1] + sumv * sh[128 + lane * 4 + 1];
            ob.z = acc[6] * sc[128 + lane * 4 + 2] + sumv * sh[128 + lane * 4 + 2];
            ob.w = acc[7] * sc[128 + lane * 4 + 3] + sumv * sh[128 + lane * 4 + 3];
        } else {
            oa.x = acc[0]; oa.y = acc[1]; oa.z = acc[2]; oa.w = acc[3];
            ob.x = acc[4]; ob.y = acc[5]; ob.z = acc[6]; ob.w = acc[7];
        }
        *reinterpret_cast<float4*>(dst + lane * 4) = oa;
        *reinterpret_cast<float4*>(dst + 128 + lane * 4) = ob;
    }
}

template <int C, int FOLD>
__global__ void conv_kernel(int in_off, int out_off) {
    int row = (blockIdx.x * blockDim.x + threadIdx.x) >> 5;
    if (row >= NN) return;
    int lane = threadIdx.x & 31;
    const float* base = d_J + in_off;
    float* dst = d_J + (size_t)row * JC + out_off;
    float acc[C];

    float sv = gather_one<C>(d_e1, __ldg(d_ptr1 + row), __ldg(d_ptr1 + row + 1), base, lane, acc);
    store_acc<C, FOLD>(dst, lane, acc, sv);

    sv = gather_one<C>(d_e2, __ldg(d_ptr2 + row), __ldg(d_ptr2 + row + 1), base, lane, acc);
    store_acc<C, FOLD>(dst + 32 * C, lane, acc, sv);
}

// ---------------- BatchNorm stats + finalize ----------------
__global__ void bn_stats_kernel(int off, int D, int statOff, int rowsPerBlock) {
    int f = threadIdx.x;
    int r0 = blockIdx.x * rowsPerBlock;
    int r1 = r0 + rowsPerBlock;
    if (r1 > NN) r1 = NN;
    float s = 0.f, q = 0.f;
    for (int r = r0; r < r1; r++) {
        float v = d_J[(size_t)r * JC + off + f];
        s += v;
        q += v * v;
    }
    atomicAdd(&d_stats[statOff + f], (double)s);
    atomicAdd(&d_stats[statOff + D + f], (double)q);
}

__global__ void bn_finalize_kernel(int D, int statOff, int which,
                                   const float* __restrict__ gamma,
                                   const float* __restrict__ beta) {
    int f = threadIdx.x;
    if (f >= D) return;
    double m = d_stats[statOff + f] / (double)NN;
    double var = d_stats[statOff + D + f] / (double)NN - m * m;
    float sc = gamma[f] * rsqrtf((float)var + BN_EPS);
    float sh = beta[f] - (float)m * sc;
    if (which) { d_scale1[f] = sc; d_shift1[f] = sh; }
    else       { d_scale0[f] = sc; d_shift0[f] = sh; }
}

// ---------------- head prescale: W' = sc*W, b' = b + sum sh*W ----------------
__global__ void head_prescale_kernel(const float* __restrict__ W,
                                     const float* __restrict__ b) {
    // one block, 1024 threads: c = t%32, fgroup = t/32
    __shared__ float red[32][33];
    int t = threadIdx.x;
    int c = t & 31;
    int fg = t >> 5;   // 0..31
    float partial = 0.f;
    for (int f = fg; f < JC; f += 32) {
        float w = W[f * OUTC + c];
        float sc = 1.f, sh = 0.f;
        if (f >= 64 && f < 192) { sc = d_scale0[f - 64]; sh = d_shift0[f - 64]; }
        else if (f >= 192 && f < 448) { sc = d_scale1[f - 192]; sh = d_shift1[f - 192]; }
        d_Wh2[f * OUTC + c] = w * sc;
        partial += sh * w;
    }
    red[fg][c] = partial;
    __syncthreads();
    if (fg == 0) {
        float s = 0.f;
#pragma unroll
        for (int k = 0; k < 32; k++) s += red[k][c];
        d_bh2[c] = b[c] + s;
    }
}

// ---------------- head: out = J @ W' + b'  (128 rows/block, 4x4 per thread) ----------------
#define KT 48
__global__ void head_kernel(float* __restrict__ out) {
    __shared__ float xs[KT][132];   // [kk][row], padded stride
    __shared__ float Ws[KT][32];
    const int tid = threadIdx.x;    // 256
    const int tx = tid & 7;         // col group: cols tx*4..tx*4+3
    const int ty = tid >> 3;        // row group: rows ty*4..ty*4+3 (0..31)
    const int row0 = blockIdx.x * 128;

    float acc[4][4];
#pragma unroll
    for (int i = 0; i < 4; i++)
#pragma unroll
        for (int j = 0; j < 4; j++) acc[i][j] = 0.f;

    for (int kt = 0; kt < JC / KT; kt++) {
        // load xs transposed: 128 rows x KT cols, as float4 along K
#pragma unroll
        for (int k = 0; k < 6; k++) {
            int idx4 = tid + k * 256;            // 0..1535
            int kk4 = idx4 % (KT / 4);
            int r = idx4 / (KT / 4);
            float4 v = make_float4(0.f, 0.f, 0.f, 0.f);
            int row = row0 + r;
            if (row < NN)
                v = *reinterpret_cast<const float4*>(d_J + (size_t)row * JC + kt * KT + kk4 * 4);
            xs[kk4 * 4 + 0][r] = v.x;
            xs[kk4 * 4 + 1][r] = v.y;
            xs[kk4 * 4 + 2][r] = v.z;
            xs[kk4 * 4 + 3][r] = v.w;
        }
#pragma unroll
        for (int k = 0; k < 6; k++) {
            int idx = tid + k * 256;             // 0..1535
            int fl = idx >> 5;
            int c = idx & 31;
            Ws[fl][c] = d_Wh2[(kt * KT + fl) * OUTC + c];
        }
        __syncthreads();
#pragma unroll 8
        for (int kk = 0; kk < KT; kk++) {
            float4 xv = *reinterpret_cast<const float4*>(&xs[kk][ty * 4]);
            float4 wv = *reinterpret_cast<const float4*>(&Ws[kk][tx * 4]);
            float xr[4] = {xv.x, xv.y, xv.z, xv.w};
            float wc[4] = {wv.x, wv.y, wv.z, wv.w};
#pragma unroll
            for (int i = 0; i < 4; i++)
#pragma unroll
                for (int j = 0; j < 4; j++) acc[i][j] += xr[i] * wc[j];
        }
        __syncthreads();
    }

    float4 bb = *reinterpret_cast<const float4*>(d_bh2 + tx * 4);
    float bc[4] = {bb.x, bb.y, bb.z, bb.w};
#pragma unroll
    for (int i = 0; i < 4; i++) {
        int row = row0 + ty * 4 + i;
        if (row < NN) {
            float4 o = make_float4(acc[i][0] + bc[0], acc[i][1] + bc[1],
                                   acc[i][2] + bc[2], acc[i][3] + bc[3]);
            *reinterpret_cast<float4*>(out + (size_t)row * OUTC + tx * 4) = o;
        }
    }
}

extern "C" void kernel_launch(void* const* d_in, const int* in_sizes, int n_in,
                              void* d_out, int out_size) {
    const float* x   = (const float*)d_in[0];
    const int*   e1r = (const int*)d_in[1];
    const int*   e1c = (const int*)d_in[2];
    const float* e1v = (const float*)d_in[3];
    const int*   e2r = (const int*)d_in[4];
    const int*   e2c = (const int*)d_in[5];
    const float* e2v = (const float*)d_in[6];
    const float* We  = (const float*)d_in[7];
    const float* be  = (const float*)d_in[8];
    const float* g0  = (const float*)d_in[9];
    const float* b0  = (const float*)d_in[10];
    const float* g1  = (const float*)d_in[11];
    const float* b1  = (const float*)d_in[12];
    const float* Wh  = (const float*)d_in[13];
    const float* bh  = (const float*)d_in[14];
    float* out = (float*)d_out;

    const int E1 = in_sizes[1];
    const int E2 = in_sizes[4];

    // side stream + events, created once on the (non-capturing) first call
    static cudaStream_t s2 = nullptr;
    static cudaEvent_t evA = nullptr, evB = nullptr;
    if (!s2) {
        cudaStreamCreateWithFlags(&s2, cudaStreamNonBlocking);
        cudaEventCreateWithFlags(&evA, cudaEventDisableTiming);
        cudaEventCreateWithFlags(&evB, cudaEventDisableTiming);
    }

    // fork: binning on s2, embed on default stream
    cudaEventRecord(evA, 0);
    cudaStreamWaitEvent(s2, evA, 0);

    zero_small_kernel<<<(NN + 255) / 256, 256, 0, s2>>>();
    hist_kernel<<<(E1 + 255) / 256, 256, 0, s2>>>(e1r, E1, 0);
    hist_kernel<<<(E2 + 255) / 256, 256, 0, s2>>>(e2r, E2, 1);
    scan_partial_kernel<<<2 * NBLK, 256, 0, s2>>>();
    scan_tops_kernel<<<1, 512, 0, s2>>>();
    scan_add_kernel<<<2 * NBLK, 256, 0, s2>>>();
    scatter_kernel<<<(E1 + 255) / 256, 256, 0, s2>>>(e1r, e1c, e1v, E1, 0);
    scatter_kernel<<<(E2 + 255) / 256, 256, 0, s2>>>(e2r, e2c, e2v, E2, 1);

    embed_kernel<<<NN / 16, dim3(64, 4)>>>(x, We, be);

    cudaEventRecord(evB, s2);
    cudaStreamWaitEvent(0, evB, 0);

    const int gblocks = (NN + 7) / 8;

    // conv1: h -> c0 raw, cols [64,192)
    conv_kernel<2, 0><<<gblocks, 256>>>(0, 64);

    // bn0 stats over raw c0
    bn_stats_kernel<<<(NN + 127) / 128, 128>>>(64, 128, 0, 128);
    bn_finalize_kernel<<<1, 128>>>(128, 0, 0, g0, b0);

    // conv2: bn0(c0) -> c1 raw, cols [192,448) (BN folded into gather)
    conv_kernel<4, 1><<<gblocks, 256>>>(64, 192);

    // bn1 stats over raw c1
    bn_stats_kernel<<<(NN + 127) / 128, 256>>>(192, 256, 256, 128);
    bn_finalize_kernel<<<1, 256>>>(256, 256, 1, g1, b1);

    // conv3: bn1(c1) -> c2, cols [448,960)
    conv_kernel<8, 2><<<gblocks, 256>>>(192, 448);

    // head: prescale W (fold bn into weights), then GEMM on raw J
    head_prescale_kernel<<<1, 1024>>>(Wh, bh);
    head_kernel<<<(NN + 127) / 128, 256>>>(out);
}